// round 1
// baseline (speedup 1.0000x reference)
#include <cuda_runtime.h>
#include <cstdint>

#define BATCH   2048
#define RNK     32
#define NVEC    8192
#define H_INIT  256
#define H_DYN   512
#define D_DYN   98
#define D_INIT  96
#define NSTEP   31          // STEPS-1 RK4 steps

// 2 * log2(e): fold tanh's exp(2z) = 2^(2*log2e*z) scaling into the weights.
#define L2E2 2.885390081777927f

// Pre-transposed, pre-scaled weights. [k][u] layout => lane-coalesced loads.
__device__ float g_WtDyn[D_DYN * H_DYN];
__device__ float g_WtInit[D_INIT * H_INIT];

__global__ void prep_kernel(const float* __restrict__ Wd1,
                            const float* __restrict__ Wi1) {
    int i = blockIdx.x * blockDim.x + threadIdx.x;
    if (i < D_DYN * H_DYN) {
        int k = i / H_DYN, u = i % H_DYN;
        g_WtDyn[i] = Wd1[u * D_DYN + k] * L2E2;
    }
    int j = i - D_DYN * H_DYN;
    if (j >= 0 && j < D_INIT * H_INIT) {
        int k = j / H_INIT, u = j % H_INIT;
        g_WtInit[j] = Wi1[u * D_INIT + k] * L2E2;
    }
}

__device__ __forceinline__ float ex2f(float a) {
    float r; asm("ex2.approx.f32 %0, %1;" : "=f"(r) : "f"(a)); return r;
}
__device__ __forceinline__ float rcpf(float a) {
    float r; asm("rcp.approx.f32 %0, %1;" : "=f"(r) : "f"(a)); return r;
}

__global__ void __launch_bounds__(128, 4) node_kernel(
    const int*   __restrict__ b_i_raw,   // int32 or int64 (sniffed)
    const float* __restrict__ b_t_n,
    const float* __restrict__ U0,
    const float* __restrict__ U1,
    const float* __restrict__ U2,
    const float* __restrict__ bi1,
    const float* __restrict__ Wi2,
    const float* __restrict__ bi2,
    const float* __restrict__ bd1,
    const float* __restrict__ Wd2,
    const float* __restrict__ bd2,
    float* __restrict__ out)
{
    __shared__ float uv[4][96];
    const int w    = threadIdx.x >> 5;
    const int lane = threadIdx.x & 31;
    const int s    = blockIdx.x * 4 + w;
    const int ub   = lane * 4;

    // --- index dtype sniff: int64 rows have zero high words ---
    bool is64 = ((b_i_raw[1] | b_i_raw[3] | b_i_raw[5]) == 0);
    int i0, i1, i2;
    if (is64) {
        i0 = b_i_raw[(s * 3 + 0) * 2];
        i1 = b_i_raw[(s * 3 + 1) * 2];
        i2 = b_i_raw[(s * 3 + 2) * 2];
    } else {
        i0 = b_i_raw[s * 3 + 0];
        i1 = b_i_raw[s * 3 + 1];
        i2 = b_i_raw[s * 3 + 2];
    }

    // --- gather Uvec (96) into shared; RNK==32 -> one lane per element ---
    uv[w][lane]      = U0[(size_t)i0 * RNK + lane];
    uv[w][32 + lane] = U1[(size_t)i1 * RNK + lane];
    uv[w][64 + lane] = U2[(size_t)i2 * RNK + lane];
    __syncwarp();

    // ======================= dyn-net precompute =======================
    // c[u] = (bd1[u] + Wd1[u,2:]·Uvec) * 2log2e    (per-sample constant)
    float c[16];
    #pragma unroll
    for (int g = 0; g < 4; g++) {
        float4 bv = *(const float4*)(bd1 + g * 128 + ub);
        c[g*4+0] = bv.x * L2E2; c[g*4+1] = bv.y * L2E2;
        c[g*4+2] = bv.z * L2E2; c[g*4+3] = bv.w * L2E2;
    }
    #pragma unroll 2
    for (int k = 0; k < 96; k++) {
        float uk = uv[w][k];
        const float* row = g_WtDyn + (k + 2) * H_DYN + ub;
        #pragma unroll
        for (int g = 0; g < 4; g++) {
            float4 wv = *(const float4*)(row + g * 128);
            c[g*4+0] = fmaf(wv.x, uk, c[g*4+0]);
            c[g*4+1] = fmaf(wv.y, uk, c[g*4+1]);
            c[g*4+2] = fmaf(wv.z, uk, c[g*4+2]);
            c[g*4+3] = fmaf(wv.w, uk, c[g*4+3]);
        }
    }

    const float scaleT = b_t_n[s];
    float w0l[16], w1l[16], w2m[16];
    float sumw2 = 0.f;
    #pragma unroll
    for (int g = 0; g < 4; g++) {
        float4 a0 = *(const float4*)(g_WtDyn + 0 * H_DYN + g * 128 + ub);
        float4 a1 = *(const float4*)(g_WtDyn + 1 * H_DYN + g * 128 + ub);
        float4 a2 = *(const float4*)(Wd2 + g * 128 + ub);
        w0l[g*4+0] = a0.x * scaleT; w0l[g*4+1] = a0.y * scaleT;
        w0l[g*4+2] = a0.z * scaleT; w0l[g*4+3] = a0.w * scaleT;
        w1l[g*4+0] = a1.x; w1l[g*4+1] = a1.y;
        w1l[g*4+2] = a1.z; w1l[g*4+3] = a1.w;
        w2m[g*4+0] = -2.f * a2.x; w2m[g*4+1] = -2.f * a2.y;
        w2m[g*4+2] = -2.f * a2.z; w2m[g*4+3] = -2.f * a2.w;
        sumw2 += (a2.x + a2.y) + (a2.z + a2.w);
    }

    // ======================= init net: x0 =======================
    float ai[8];
    #pragma unroll
    for (int g = 0; g < 2; g++) {
        float4 bv = *(const float4*)(bi1 + g * 128 + ub);
        ai[g*4+0] = bv.x * L2E2; ai[g*4+1] = bv.y * L2E2;
        ai[g*4+2] = bv.z * L2E2; ai[g*4+3] = bv.w * L2E2;
    }
    #pragma unroll 2
    for (int k = 0; k < 96; k++) {
        float uk = uv[w][k];
        const float* row = g_WtInit + k * H_INIT + ub;
        #pragma unroll
        for (int g = 0; g < 2; g++) {
            float4 wv = *(const float4*)(row + g * 128);
            ai[g*4+0] = fmaf(wv.x, uk, ai[g*4+0]);
            ai[g*4+1] = fmaf(wv.y, uk, ai[g*4+1]);
            ai[g*4+2] = fmaf(wv.z, uk, ai[g*4+2]);
            ai[g*4+3] = fmaf(wv.w, uk, ai[g*4+3]);
        }
    }
    float p0 = 0.f;
    #pragma unroll
    for (int g = 0; g < 2; g++) {
        float4 wv = *(const float4*)(Wi2 + g * 128 + ub);
        float r;
        r = rcpf(ex2f(ai[g*4+0]) + 1.f); p0 = fmaf(1.f - 2.f * r, wv.x, p0);
        r = rcpf(ex2f(ai[g*4+1]) + 1.f); p0 = fmaf(1.f - 2.f * r, wv.y, p0);
        r = rcpf(ex2f(ai[g*4+2]) + 1.f); p0 = fmaf(1.f - 2.f * r, wv.z, p0);
        r = rcpf(ex2f(ai[g*4+3]) + 1.f); p0 = fmaf(1.f - 2.f * r, wv.w, p0);
    }
    #pragma unroll
    for (int off = 16; off > 0; off >>= 1)
        p0 += __shfl_xor_sync(0xffffffffu, p0, off);

    float x = p0 + bi2[0];
    const float bd2v = bd2[0];

    // ======================= RK4 loop =======================
    // dyn(t,x) = (sum_u tanh(c_u + w0l_u*t + w1l_u*x) * Wd2_u + bd2) * scaleT
    // tanh(z) via 1 - 2/(2^(2*log2e*z) + 1); scaling prefolded into c/w0l/w1l.
    auto feval = [&](float t, float xv) -> float {
        float acc0 = 0.f, acc1 = 0.f;
        #pragma unroll
        for (int i = 0; i < 16; i += 2) {
            float a0 = fmaf(w0l[i],     t, fmaf(w1l[i],     xv, c[i]));
            float a1 = fmaf(w0l[i + 1], t, fmaf(w1l[i + 1], xv, c[i + 1]));
            float r0 = rcpf(ex2f(a0) + 1.f);
            float r1 = rcpf(ex2f(a1) + 1.f);
            acc0 = fmaf(r0, w2m[i],     acc0);
            acc1 = fmaf(r1, w2m[i + 1], acc1);
        }
        float p = (acc0 + acc1) + sumw2;
        #pragma unroll
        for (int off = 16; off > 0; off >>= 1)
            p += __shfl_xor_sync(0xffffffffu, p, off);
        return (p + bd2v) * scaleT;
    };

    const float hh = 1.f / 31.f;
    #pragma unroll 1
    for (int stp = 0; stp < NSTEP; stp++) {
        float t0 = (float)stp * hh;
        float k1 = feval(t0,             x);
        float k2 = feval(t0 + 0.5f * hh, fmaf(0.5f * hh, k1, x));
        float k3 = feval(t0 + 0.5f * hh, fmaf(0.5f * hh, k2, x));
        float k4 = feval(t0 + hh,        fmaf(hh, k3, x));
        x += (hh / 6.f) * (k1 + 2.f * (k2 + k3) + k4);
    }

    if (lane == 0) out[s] = x;
}

extern "C" void kernel_launch(void* const* d_in, const int* in_sizes, int n_in,
                              void* d_out, int out_size) {
    const int*   b_i  = (const int*)  d_in[0];
    const float* b_t  = (const float*)d_in[1];
    const float* U0   = (const float*)d_in[2];
    const float* U1   = (const float*)d_in[3];
    const float* U2   = (const float*)d_in[4];
    const float* Wi1  = (const float*)d_in[5];
    const float* bi1  = (const float*)d_in[6];
    const float* Wi2  = (const float*)d_in[7];
    const float* bi2  = (const float*)d_in[8];
    const float* Wd1  = (const float*)d_in[9];
    const float* bd1  = (const float*)d_in[10];
    const float* Wd2  = (const float*)d_in[11];
    const float* bd2  = (const float*)d_in[12];

    int tot = D_DYN * H_DYN + D_INIT * H_INIT;
    prep_kernel<<<(tot + 255) / 256, 256>>>(Wd1, Wi1);
    node_kernel<<<BATCH / 4, 128>>>(b_i, b_t, U0, U1, U2,
                                    bi1, Wi2, bi2, bd1, Wd2, bd2,
                                    (float*)d_out);
}

// round 2
// speedup vs baseline: 1.5337x; 1.5337x over previous
#include <cuda_runtime.h>
#include <cstdint>

#define BATCH   2048
#define RNK     32
#define NVEC    8192
#define H_INIT  256
#define H_DYN   512
#define D_DYN   98
#define D_INIT  96
#define NSTEP   31          // STEPS-1 RK4 steps

// Pre-transposed weights. [k][u] layout => lane-coalesced loads.
__device__ float g_WtDyn[D_DYN * H_DYN];
__device__ float g_WtInit[D_INIT * H_INIT];

__global__ void prep_kernel(const float* __restrict__ Wd1,
                            const float* __restrict__ Wi1) {
    int i = blockIdx.x * blockDim.x + threadIdx.x;
    if (i < D_DYN * H_DYN) {
        int k = i / H_DYN, u = i % H_DYN;
        g_WtDyn[i] = Wd1[u * D_DYN + k];
    }
    int j = i - D_DYN * H_DYN;
    if (j >= 0 && j < D_INIT * H_INIT) {
        int k = j / H_INIT, u = j % H_INIT;
        g_WtInit[j] = Wi1[u * D_INIT + k];
    }
}

__device__ __forceinline__ float tanhf_fast(float a) {
    float r; asm("tanh.approx.f32 %0, %1;" : "=f"(r) : "f"(a)); return r;
}

__global__ void __launch_bounds__(128, 4) node_kernel(
    const int*   __restrict__ b_i_raw,   // int32 or int64 (sniffed)
    const float* __restrict__ b_t_n,
    const float* __restrict__ U0,
    const float* __restrict__ U1,
    const float* __restrict__ U2,
    const float* __restrict__ bi1,
    const float* __restrict__ Wi2,
    const float* __restrict__ bi2,
    const float* __restrict__ bd1,
    const float* __restrict__ Wd2,
    const float* __restrict__ bd2,
    float* __restrict__ out)
{
    __shared__ float uv[4][96];
    const int w    = threadIdx.x >> 5;
    const int lane = threadIdx.x & 31;
    const int s    = blockIdx.x * 4 + w;
    const int ub   = lane * 4;

    // --- index dtype sniff: int64 rows have zero high words ---
    bool is64 = ((b_i_raw[1] | b_i_raw[3] | b_i_raw[5]) == 0);
    int i0, i1, i2;
    if (is64) {
        i0 = b_i_raw[(s * 3 + 0) * 2];
        i1 = b_i_raw[(s * 3 + 1) * 2];
        i2 = b_i_raw[(s * 3 + 2) * 2];
    } else {
        i0 = b_i_raw[s * 3 + 0];
        i1 = b_i_raw[s * 3 + 1];
        i2 = b_i_raw[s * 3 + 2];
    }

    // --- gather Uvec (96) into shared; RNK==32 -> one lane per element ---
    uv[w][lane]      = U0[(size_t)i0 * RNK + lane];
    uv[w][32 + lane] = U1[(size_t)i1 * RNK + lane];
    uv[w][64 + lane] = U2[(size_t)i2 * RNK + lane];
    __syncwarp();

    // ======================= dyn-net precompute =======================
    // c[u] = bd1[u] + Wd1[u,2:]·Uvec      (per-sample constant)
    float c[16];
    #pragma unroll
    for (int g = 0; g < 4; g++) {
        float4 bv = *(const float4*)(bd1 + g * 128 + ub);
        c[g*4+0] = bv.x; c[g*4+1] = bv.y;
        c[g*4+2] = bv.z; c[g*4+3] = bv.w;
    }
    #pragma unroll 2
    for (int k = 0; k < 96; k++) {
        float uk = uv[w][k];
        const float* row = g_WtDyn + (k + 2) * H_DYN + ub;
        #pragma unroll
        for (int g = 0; g < 4; g++) {
            float4 wv = *(const float4*)(row + g * 128);
            c[g*4+0] = fmaf(wv.x, uk, c[g*4+0]);
            c[g*4+1] = fmaf(wv.y, uk, c[g*4+1]);
            c[g*4+2] = fmaf(wv.z, uk, c[g*4+2]);
            c[g*4+3] = fmaf(wv.w, uk, c[g*4+3]);
        }
    }

    const float scaleT = b_t_n[s];
    float w0l[16], w1l[16], w2l[16];
    #pragma unroll
    for (int g = 0; g < 4; g++) {
        float4 a0 = *(const float4*)(g_WtDyn + 0 * H_DYN + g * 128 + ub);
        float4 a1 = *(const float4*)(g_WtDyn + 1 * H_DYN + g * 128 + ub);
        float4 a2 = *(const float4*)(Wd2 + g * 128 + ub);
        w0l[g*4+0] = a0.x * scaleT; w0l[g*4+1] = a0.y * scaleT;
        w0l[g*4+2] = a0.z * scaleT; w0l[g*4+3] = a0.w * scaleT;
        w1l[g*4+0] = a1.x; w1l[g*4+1] = a1.y;
        w1l[g*4+2] = a1.z; w1l[g*4+3] = a1.w;
        w2l[g*4+0] = a2.x; w2l[g*4+1] = a2.y;
        w2l[g*4+2] = a2.z; w2l[g*4+3] = a2.w;
    }

    // ======================= init net: x0 =======================
    float ai[8];
    #pragma unroll
    for (int g = 0; g < 2; g++) {
        float4 bv = *(const float4*)(bi1 + g * 128 + ub);
        ai[g*4+0] = bv.x; ai[g*4+1] = bv.y;
        ai[g*4+2] = bv.z; ai[g*4+3] = bv.w;
    }
    #pragma unroll 2
    for (int k = 0; k < 96; k++) {
        float uk = uv[w][k];
        const float* row = g_WtInit + k * H_INIT + ub;
        #pragma unroll
        for (int g = 0; g < 2; g++) {
            float4 wv = *(const float4*)(row + g * 128);
            ai[g*4+0] = fmaf(wv.x, uk, ai[g*4+0]);
            ai[g*4+1] = fmaf(wv.y, uk, ai[g*4+1]);
            ai[g*4+2] = fmaf(wv.z, uk, ai[g*4+2]);
            ai[g*4+3] = fmaf(wv.w, uk, ai[g*4+3]);
        }
    }
    float p0 = 0.f;
    #pragma unroll
    for (int g = 0; g < 2; g++) {
        float4 wv = *(const float4*)(Wi2 + g * 128 + ub);
        p0 = fmaf(tanhf_fast(ai[g*4+0]), wv.x, p0);
        p0 = fmaf(tanhf_fast(ai[g*4+1]), wv.y, p0);
        p0 = fmaf(tanhf_fast(ai[g*4+2]), wv.z, p0);
        p0 = fmaf(tanhf_fast(ai[g*4+3]), wv.w, p0);
    }
    #pragma unroll
    for (int off = 16; off > 0; off >>= 1)
        p0 += __shfl_xor_sync(0xffffffffu, p0, off);

    float x = p0 + bi2[0];
    const float bd2v = bd2[0];

    // ======================= RK4 loop =======================
    // dyn(t,x) = (sum_u tanh(c_u + w0l_u*t + w1l_u*x) * w2_u + bd2) * scaleT
    auto feval = [&](float t, float xv) -> float {
        float acc0 = 0.f, acc1 = 0.f, acc2 = 0.f, acc3 = 0.f;
        #pragma unroll
        for (int i = 0; i < 16; i += 4) {
            float a0 = fmaf(w0l[i],     t, fmaf(w1l[i],     xv, c[i]));
            float a1 = fmaf(w0l[i + 1], t, fmaf(w1l[i + 1], xv, c[i + 1]));
            float a2 = fmaf(w0l[i + 2], t, fmaf(w1l[i + 2], xv, c[i + 2]));
            float a3 = fmaf(w0l[i + 3], t, fmaf(w1l[i + 3], xv, c[i + 3]));
            acc0 = fmaf(tanhf_fast(a0), w2l[i],     acc0);
            acc1 = fmaf(tanhf_fast(a1), w2l[i + 1], acc1);
            acc2 = fmaf(tanhf_fast(a2), w2l[i + 2], acc2);
            acc3 = fmaf(tanhf_fast(a3), w2l[i + 3], acc3);
        }
        float p = (acc0 + acc1) + (acc2 + acc3);
        #pragma unroll
        for (int off = 16; off > 0; off >>= 1)
            p += __shfl_xor_sync(0xffffffffu, p, off);
        return (p + bd2v) * scaleT;
    };

    const float hh = 1.f / 31.f;
    #pragma unroll 1
    for (int stp = 0; stp < NSTEP; stp++) {
        float t0 = (float)stp * hh;
        float k1 = feval(t0,             x);
        float k2 = feval(t0 + 0.5f * hh, fmaf(0.5f * hh, k1, x));
        float k3 = feval(t0 + 0.5f * hh, fmaf(0.5f * hh, k2, x));
        float k4 = feval(t0 + hh,        fmaf(hh, k3, x));
        x += (hh / 6.f) * (k1 + 2.f * (k2 + k3) + k4);
    }

    if (lane == 0) out[s] = x;
}

extern "C" void kernel_launch(void* const* d_in, const int* in_sizes, int n_in,
                              void* d_out, int out_size) {
    const int*   b_i  = (const int*)  d_in[0];
    const float* b_t  = (const float*)d_in[1];
    const float* U0   = (const float*)d_in[2];
    const float* U1   = (const float*)d_in[3];
    const float* U2   = (const float*)d_in[4];
    const float* Wi1  = (const float*)d_in[5];
    const float* bi1  = (const float*)d_in[6];
    const float* Wi2  = (const float*)d_in[7];
    const float* bi2  = (const float*)d_in[8];
    const float* Wd1  = (const float*)d_in[9];
    const float* bd1  = (const float*)d_in[10];
    const float* Wd2  = (const float*)d_in[11];
    const float* bd2  = (const float*)d_in[12];

    int tot = D_DYN * H_DYN + D_INIT * H_INIT;
    prep_kernel<<<(tot + 255) / 256, 256>>>(Wd1, Wi1);
    node_kernel<<<BATCH / 4, 128>>>(b_i, b_t, U0, U1, U2,
                                    bi1, Wi2, bi2, bd1, Wd2, bd2,
                                    (float*)d_out);
}